// round 9
// baseline (speedup 1.0000x reference)
#include <cuda_runtime.h>
#include <math.h>

// Problem constants (fixed by the reference)
#define BB 8
#define NN 512
#define NUM_GT 64
#define CC 16
#define FHH 16
#define FWW 16
#define ZW 1.1f
#define ZH 1.1f

#define NANCH (BB * NN)                        // 4096
#define LBL_ELEMS ((size_t)NANCH * CC * 256)   // 16,777,216
#define OFF_ELEMS ((size_t)NANCH * 4 * 256)    // 4,194,304
#define OFF_BASE  LBL_ELEMS
#define MSK_BASE  (LBL_ELEMS + OFF_ELEMS)      // 20,971,520

__global__ void __launch_bounds__(256, 8)
rcnn_bindet_kernel(const float4* __restrict__ boxes,     // (B*N) xyxy
                   const float*  __restrict__ gt,        // (B, NUM_GT, 5)
                   const int*    __restrict__ flag,      // (B*N)
                   const int*    __restrict__ gid,       // (B*N)
                   float* __restrict__ out)
{
    const int a = blockIdx.x;       // anchor index (b*N + n)
    const int b = a >> 9;           // / NN
    const int t = threadIdx.x;      // 0..255

    // ---- per-anchor scalar setup (uniform across block) ----
    const float4 bx = __ldg(&boxes[a]);
    int g = __ldg(&gid[a]);
    g = min(max(g, 0), NUM_GT - 1);
    const float* grow = gt + ((size_t)b * NUM_GT + g) * 5;
    const float g0 = __ldg(grow + 0), g1 = __ldg(grow + 1);
    const float g2 = __ldg(grow + 2), g3 = __ldg(grow + 3);
    const float label = __ldg(grow + 4);

    const float cx0 = (bx.x + bx.z) * 0.5f;
    const float cy0 = (bx.y + bx.w) * 0.5f;
    const float w   = (bx.z - bx.x) * ZW;
    const float h   = (bx.w - bx.y) * ZH;
    const float ax1 = cx0 - w * 0.5f, ax2 = cx0 + w * 0.5f;
    const float ay1 = cy0 - h * 0.5f, ay2 = cy0 + h * 0.5f;

    const float rx1 = g0 - ax1, ry1 = g1 - ay1;
    const float rx2 = g2 - ax1, ry2 = g3 - ay1;
    const float rw = rx2 - rx1, rh = ry2 - ry1;
    const float ccx = (rx1 + rx2) * 0.5f, ccy = (ry1 + ry2) * 0.5f;

    const float sw = (ax2 - ax1) * (1.0f / FWW);
    const float sh = (ay2 - ay1) * (1.0f / FHH);
    const float inv_sw = __fdividef(1.0f, sw);
    const float inv_sh = __fdividef(1.0f, sh);

    const float w_sigma = rw * 0.5f * inv_sw;
    const float h_sigma = rh * 0.5f * inv_sh;
    const float wss = fmaxf(w_sigma, 1.5f), hss = fmaxf(h_sigma, 1.5f);
    const float wsc = fmaxf(w_sigma, 0.5f), hsc = fmaxf(h_sigma, 0.5f);
    const float pw = ccx * inv_sw, ph = ccy * inv_sh;

    const bool small_box = (sw < 0.01f) || (sh < 0.01f);

    // class channel via exact float equality, like the reference
    const float lm1 = fabsf(label) - 1.0f;
    int c_lab = (int)lm1;
    if (!((float)c_lab == lm1 && c_lab >= 0 && c_lab < CC)) c_lab = -1;

    const float inv_wss = __fdividef(1.0f, wss);
    const float inv_hss = __fdividef(1.0f, hss);

    const float4 zero4 = make_float4(0.f, 0.f, 0.f, 0.f);

    // ---- offset: 256 float4 per anchor, 1 per thread (issue first) ----
    {
        float4* outO = reinterpret_cast<float4*>(out + OFF_BASE + (size_t)a * 1024);
        const int k   = t >> 6;            // 0:ox1 1:oy1 2:ox2 3:oy2
        const int pix = (t & 63) << 2;
        const int fh = pix >> 4;
        const int fw0 = pix & 15;
        float4 v = zero4;
        if (!small_box) {
            float p0;
            if (k == 0)      p0 = rx1 * inv_sw;
            else if (k == 1) p0 = ry1 * inv_sh;
            else if (k == 2) p0 = rx2 * inv_sw;
            else             p0 = ry2 * inv_sh;
            if ((k & 1) == 0) {
                v.x = p0 - ((float)fw0 + 0.5f);
                v.y = p0 - ((float)fw0 + 1.5f);
                v.z = p0 - ((float)fw0 + 2.5f);
                v.w = p0 - ((float)fw0 + 3.5f);
            } else {
                const float c0 = p0 - ((float)fh + 0.5f);
                v.x = c0; v.y = c0; v.z = c0; v.w = c0;
            }
        }
        __stcs(outO + t, v);
    }

    // ---- mask: 16 floats per anchor, threads 0..3 each write a float4 ----
    if (t < 4) {
        float4* outM = reinterpret_cast<float4*>(out + MSK_BASE + (size_t)a * CC);
        const int fl = __ldg(&flag[a]);
        const bool m1 = (fl > 0) && (label > 0.0f);
        float4 v = zero4;
        if (m1 && c_lab >= 0 && (c_lab >> 2) == t) {
            (&v.x)[c_lab & 3] = 1.0f;
        }
        __stcs(outM + t, v);
    }

    // ---- label_map: 1024 float4 per anchor, 4 per thread ----
    float4* outL = reinterpret_cast<float4*>(out + (size_t)a * (CC * 256));
    #pragma unroll
    for (int j = 0; j < 4; ++j) {
        const int f   = j * 256 + t;       // float4 index within anchor
        const int ch  = f >> 6;            // 64 float4 per channel
        float4 v = zero4;
        if (ch == c_lab && !small_box) {   // warp-uniform branch
            const int pix = (f & 63) << 2; // element within channel
            const int fh = pix >> 4;
            const int fw0 = pix & 15;
            const float dh = ph - (float)fh - 0.5f;
            const float ht = dh * inv_hss;
            const float hterm = ht * ht;
            const bool  hcond = fabsf((float)fh + 0.5f - ph) < hsc;
            float* vp = &v.x;
            #pragma unroll
            for (int i = 0; i < 4; ++i) {
                const float fwc = (float)(fw0 + i) + 0.5f;
                const float dw = pw - fwc;
                const float wt = dw * inv_wss;
                const float e = __expf(-(wt * wt + hterm));
                const bool cond = hcond && (fabsf(fwc - pw) < wsc);
                vp[i] = cond ? e : 0.0f;
            }
        }
        __stcs(outL + f, v);
    }
}

extern "C" void kernel_launch(void* const* d_in, const int* in_sizes, int n_in,
                              void* d_out, int out_size) {
    const float4* boxes = (const float4*)d_in[0];   // (B,N,4) f32
    const float*  gt    = (const float*)d_in[1];    // (B,NUM_GT,5) f32
    const int*    flag  = (const int*)d_in[2];      // (B,N) i32
    const int*    gid   = (const int*)d_in[3];      // (B,N) i32
    float* out = (float*)d_out;

    rcnn_bindet_kernel<<<NANCH, 256>>>(boxes, gt, flag, gid, out);
    (void)in_sizes; (void)n_in; (void)out_size;
}

// round 10
// speedup vs baseline: 1.0229x; 1.0229x over previous
#include <cuda_runtime.h>
#include <math.h>

// Problem constants (fixed by the reference)
#define BB 8
#define NN 512
#define NUM_GT 64
#define CC 16
#define FHH 16
#define FWW 16
#define ZW 1.1f
#define ZH 1.1f

#define NANCH (BB * NN)                        // 4096
#define LBL_ELEMS ((size_t)NANCH * CC * 256)   // 16,777,216
#define OFF_ELEMS ((size_t)NANCH * 4 * 256)    // 4,194,304
#define OFF_BASE  LBL_ELEMS
#define MSK_BASE  (LBL_ELEMS + OFF_ELEMS)      // 20,971,520

__global__ void __launch_bounds__(256, 8)
rcnn_bindet_kernel(const float4* __restrict__ boxes,     // (B*N) xyxy
                   const float*  __restrict__ gt,        // (B, NUM_GT, 5)
                   const int*    __restrict__ flag,      // (B*N)
                   const int*    __restrict__ gid,       // (B*N)
                   float* __restrict__ out)
{
    const int a = blockIdx.x;       // anchor index (b*N + n)
    const int b = a >> 9;           // / NN
    const int t = threadIdx.x;      // 0..255

    // ---- per-anchor scalar setup (uniform across block) ----
    const float4 bx = __ldg(&boxes[a]);
    int g = __ldg(&gid[a]);
    g = min(max(g, 0), NUM_GT - 1);
    const float* grow = gt + ((size_t)b * NUM_GT + g) * 5;
    const float g0 = __ldg(grow + 0), g1 = __ldg(grow + 1);
    const float g2 = __ldg(grow + 2), g3 = __ldg(grow + 3);
    const float label = __ldg(grow + 4);

    const float cx0 = (bx.x + bx.z) * 0.5f;
    const float cy0 = (bx.y + bx.w) * 0.5f;
    const float w   = (bx.z - bx.x) * ZW;
    const float h   = (bx.w - bx.y) * ZH;
    const float ax1 = cx0 - w * 0.5f, ax2 = cx0 + w * 0.5f;
    const float ay1 = cy0 - h * 0.5f, ay2 = cy0 + h * 0.5f;

    const float rx1 = g0 - ax1, ry1 = g1 - ay1;
    const float rx2 = g2 - ax1, ry2 = g3 - ay1;
    const float rw = rx2 - rx1, rh = ry2 - ry1;
    const float ccx = (rx1 + rx2) * 0.5f, ccy = (ry1 + ry2) * 0.5f;

    const float sw = (ax2 - ax1) * (1.0f / FWW);
    const float sh = (ay2 - ay1) * (1.0f / FHH);
    const float inv_sw = __fdividef(1.0f, sw);
    const float inv_sh = __fdividef(1.0f, sh);

    const float w_sigma = rw * 0.5f * inv_sw;
    const float h_sigma = rh * 0.5f * inv_sh;
    const float wss = fmaxf(w_sigma, 1.5f), hss = fmaxf(h_sigma, 1.5f);
    const float wsc = fmaxf(w_sigma, 0.5f), hsc = fmaxf(h_sigma, 0.5f);
    const float pw = ccx * inv_sw, ph = ccy * inv_sh;

    const bool small_box = (sw < 0.01f) || (sh < 0.01f);

    // class channel via exact float equality, like the reference
    const float lm1 = fabsf(label) - 1.0f;
    int c_lab = (int)lm1;
    if (!((float)c_lab == lm1 && c_lab >= 0 && c_lab < CC)) c_lab = -1;

    const float inv_wss = __fdividef(1.0f, wss);
    const float inv_hss = __fdividef(1.0f, hss);

    const float4 zero4 = make_float4(0.f, 0.f, 0.f, 0.f);

    // ---- offset: 256 float4 per anchor, 1 per thread (issue first) ----
    {
        float4* outO = reinterpret_cast<float4*>(out + OFF_BASE + (size_t)a * 1024);
        const int k   = t >> 6;            // 0:ox1 1:oy1 2:ox2 3:oy2
        const int pix = (t & 63) << 2;
        const int fh = pix >> 4;
        const int fw0 = pix & 15;
        float4 v = zero4;
        if (!small_box) {
            float p0;
            if (k == 0)      p0 = rx1 * inv_sw;
            else if (k == 1) p0 = ry1 * inv_sh;
            else if (k == 2) p0 = rx2 * inv_sw;
            else             p0 = ry2 * inv_sh;
            if ((k & 1) == 0) {
                v.x = p0 - ((float)fw0 + 0.5f);
                v.y = p0 - ((float)fw0 + 1.5f);
                v.z = p0 - ((float)fw0 + 2.5f);
                v.w = p0 - ((float)fw0 + 3.5f);
            } else {
                const float c0 = p0 - ((float)fh + 0.5f);
                v.x = c0; v.y = c0; v.z = c0; v.w = c0;
            }
        }
        __stcs(outO + t, v);
    }

    // ---- mask: 16 floats per anchor, threads 0..3 each write a float4 ----
    if (t < 4) {
        float4* outM = reinterpret_cast<float4*>(out + MSK_BASE + (size_t)a * CC);
        const int fl = __ldg(&flag[a]);
        const bool m1 = (fl > 0) && (label > 0.0f);
        float4 v = zero4;
        if (m1 && c_lab >= 0 && (c_lab >> 2) == t) {
            (&v.x)[c_lab & 3] = 1.0f;
        }
        __stcs(outM + t, v);
    }

    // ---- label_map: 1024 float4 per anchor, 4 per thread ----
    float4* outL = reinterpret_cast<float4*>(out + (size_t)a * (CC * 256));
    #pragma unroll
    for (int j = 0; j < 4; ++j) {
        const int f   = j * 256 + t;       // float4 index within anchor
        const int ch  = f >> 6;            // 64 float4 per channel
        float4 v = zero4;
        if (ch == c_lab && !small_box) {   // warp-uniform branch
            const int pix = (f & 63) << 2; // element within channel
            const int fh = pix >> 4;
            const int fw0 = pix & 15;
            const float dh = ph - (float)fh - 0.5f;
            const float ht = dh * inv_hss;
            const float hterm = ht * ht;
            const bool  hcond = fabsf((float)fh + 0.5f - ph) < hsc;
            float* vp = &v.x;
            #pragma unroll
            for (int i = 0; i < 4; ++i) {
                const float fwc = (float)(fw0 + i) + 0.5f;
                const float dw = pw - fwc;
                const float wt = dw * inv_wss;
                const float e = __expf(-(wt * wt + hterm));
                const bool cond = hcond && (fabsf(fwc - pw) < wsc);
                vp[i] = cond ? e : 0.0f;
            }
        }
        __stcs(outL + f, v);
    }
}

extern "C" void kernel_launch(void* const* d_in, const int* in_sizes, int n_in,
                              void* d_out, int out_size) {
    const float4* boxes = (const float4*)d_in[0];   // (B,N,4) f32
    const float*  gt    = (const float*)d_in[1];    // (B,NUM_GT,5) f32
    const int*    flag  = (const int*)d_in[2];      // (B,N) i32
    const int*    gid   = (const int*)d_in[3];      // (B,N) i32
    float* out = (float*)d_out;

    rcnn_bindet_kernel<<<NANCH, 256>>>(boxes, gt, flag, gid, out);
    (void)in_sizes; (void)n_in; (void)out_size;
}

// round 11
// speedup vs baseline: 1.1555x; 1.1296x over previous
#include <cuda_runtime.h>
#include <math.h>

// Problem constants (fixed by the reference)
#define BB 8
#define NN 512
#define NUM_GT 64
#define CC 16
#define FHH 16
#define FWW 16
#define ZW 1.1f
#define ZH 1.1f

#define NANCH (BB * NN)                        // 4096
#define LBL_ELEMS ((size_t)NANCH * CC * 256)   // 16,777,216
#define OFF_ELEMS ((size_t)NANCH * 4 * 256)    // 4,194,304
#define OFF_BASE  LBL_ELEMS
#define MSK_BASE  (LBL_ELEMS + OFF_ELEMS)      // 20,971,520

__global__ void __launch_bounds__(256, 8)
rcnn_bindet_kernel(const float4* __restrict__ boxes,     // (B*N) xyxy
                   const float*  __restrict__ gt,        // (B, NUM_GT, 5)
                   const int*    __restrict__ flag,      // (B*N)
                   const int*    __restrict__ gid,       // (B*N)
                   float* __restrict__ out)
{
    const int a = blockIdx.x;       // anchor index (b*N + n)
    const int b = a >> 9;           // / NN
    const int t = threadIdx.x;      // 0..255

    // ---- per-anchor scalar setup (uniform across block) ----
    const float4 bx = __ldg(&boxes[a]);
    int g = __ldg(&gid[a]);
    g = min(max(g, 0), NUM_GT - 1);
    const float* grow = gt + ((size_t)b * NUM_GT + g) * 5;
    const float g0 = __ldg(grow + 0), g1 = __ldg(grow + 1);
    const float g2 = __ldg(grow + 2), g3 = __ldg(grow + 3);
    const float label = __ldg(grow + 4);

    const float cx0 = (bx.x + bx.z) * 0.5f;
    const float cy0 = (bx.y + bx.w) * 0.5f;
    const float w   = (bx.z - bx.x) * ZW;
    const float h   = (bx.w - bx.y) * ZH;
    const float ax1 = cx0 - w * 0.5f, ax2 = cx0 + w * 0.5f;
    const float ay1 = cy0 - h * 0.5f, ay2 = cy0 + h * 0.5f;

    const float rx1 = g0 - ax1, ry1 = g1 - ay1;
    const float rx2 = g2 - ax1, ry2 = g3 - ay1;
    const float rw = rx2 - rx1, rh = ry2 - ry1;
    const float ccx = (rx1 + rx2) * 0.5f, ccy = (ry1 + ry2) * 0.5f;

    const float sw = (ax2 - ax1) * (1.0f / FWW);
    const float sh = (ay2 - ay1) * (1.0f / FHH);
    const float inv_sw = __fdividef(1.0f, sw);
    const float inv_sh = __fdividef(1.0f, sh);

    const float w_sigma = rw * 0.5f * inv_sw;
    const float h_sigma = rh * 0.5f * inv_sh;
    const float wss = fmaxf(w_sigma, 1.5f), hss = fmaxf(h_sigma, 1.5f);
    const float wsc = fmaxf(w_sigma, 0.5f), hsc = fmaxf(h_sigma, 0.5f);
    const float pw = ccx * inv_sw, ph = ccy * inv_sh;

    const bool small_box = (sw < 0.01f) || (sh < 0.01f);

    // class channel via exact float equality, like the reference
    const float lm1 = fabsf(label) - 1.0f;
    int c_lab = (int)lm1;
    if (!((float)c_lab == lm1 && c_lab >= 0 && c_lab < CC)) c_lab = -1;

    const float inv_wss = __fdividef(1.0f, wss);
    const float inv_hss = __fdividef(1.0f, hss);

    const float4 zero4 = make_float4(0.f, 0.f, 0.f, 0.f);

    // ---- offset: 256 float4 per anchor, 1 per thread (issue first) ----
    {
        float4* outO = reinterpret_cast<float4*>(out + OFF_BASE + (size_t)a * 1024);
        const int k   = t >> 6;            // 0:ox1 1:oy1 2:ox2 3:oy2
        const int pix = (t & 63) << 2;
        const int fh = pix >> 4;
        const int fw0 = pix & 15;
        float4 v = zero4;
        if (!small_box) {
            float p0;
            if (k == 0)      p0 = rx1 * inv_sw;
            else if (k == 1) p0 = ry1 * inv_sh;
            else if (k == 2) p0 = rx2 * inv_sw;
            else             p0 = ry2 * inv_sh;
            if ((k & 1) == 0) {
                v.x = p0 - ((float)fw0 + 0.5f);
                v.y = p0 - ((float)fw0 + 1.5f);
                v.z = p0 - ((float)fw0 + 2.5f);
                v.w = p0 - ((float)fw0 + 3.5f);
            } else {
                const float c0 = p0 - ((float)fh + 0.5f);
                v.x = c0; v.y = c0; v.z = c0; v.w = c0;
            }
        }
        __stcs(outO + t, v);
    }

    // ---- mask: 16 floats per anchor, threads 0..3 each write a float4 ----
    if (t < 4) {
        float4* outM = reinterpret_cast<float4*>(out + MSK_BASE + (size_t)a * CC);
        const int fl = __ldg(&flag[a]);
        const bool m1 = (fl > 0) && (label > 0.0f);
        float4 v = zero4;
        if (m1 && c_lab >= 0 && (c_lab >> 2) == t) {
            (&v.x)[c_lab & 3] = 1.0f;
        }
        __stcs(outM + t, v);
    }

    // ---- label_map: 1024 float4 per anchor, 4 per thread ----
    float4* outL = reinterpret_cast<float4*>(out + (size_t)a * (CC * 256));
    #pragma unroll
    for (int j = 0; j < 4; ++j) {
        const int f   = j * 256 + t;       // float4 index within anchor
        const int ch  = f >> 6;            // 64 float4 per channel
        float4 v = zero4;
        if (ch == c_lab && !small_box) {   // warp-uniform branch
            const int pix = (f & 63) << 2; // element within channel
            const int fh = pix >> 4;
            const int fw0 = pix & 15;
            const float dh = ph - (float)fh - 0.5f;
            const float ht = dh * inv_hss;
            const float hterm = ht * ht;
            const bool  hcond = fabsf((float)fh + 0.5f - ph) < hsc;
            float* vp = &v.x;
            #pragma unroll
            for (int i = 0; i < 4; ++i) {
                const float fwc = (float)(fw0 + i) + 0.5f;
                const float dw = pw - fwc;
                const float wt = dw * inv_wss;
                const float e = __expf(-(wt * wt + hterm));
                const bool cond = hcond && (fabsf(fwc - pw) < wsc);
                vp[i] = cond ? e : 0.0f;
            }
        }
        __stcs(outL + f, v);
    }
}

extern "C" void kernel_launch(void* const* d_in, const int* in_sizes, int n_in,
                              void* d_out, int out_size) {
    const float4* boxes = (const float4*)d_in[0];   // (B,N,4) f32
    const float*  gt    = (const float*)d_in[1];    // (B,NUM_GT,5) f32
    const int*    flag  = (const int*)d_in[2];      // (B,N) i32
    const int*    gid   = (const int*)d_in[3];      // (B,N) i32
    float* out = (float*)d_out;

    rcnn_bindet_kernel<<<NANCH, 256>>>(boxes, gt, flag, gid, out);
    (void)in_sizes; (void)n_in; (void)out_size;
}